// round 1
// baseline (speedup 1.0000x reference)
#include <cuda_runtime.h>

// Problem constants
#define NUM_EMB   1024
#define DIM       64
#define N_TOKENS  65536
#define BM        64          // tokens per block
#define PAD       66          // smem row pitch in floats (conflict-free LDS.64)

// Output layout (single fp32 buffer, tuple order flattened):
//   [0]                      loss
//   [1 .. 1+N*D)             quantized_ste  (token-major, [65536,64])
//   [1+N*D]                  perplexity
//   [2+N*D .. 2+N*D+N)       indices (as float)
#define OFF_Q     1
#define OFF_PPL   (1 + N_TOKENS*DIM)
#define OFF_IDX   (2 + N_TOKENS*DIM)

typedef unsigned long long ull;

__device__ float g_ensq[NUM_EMB];
__device__ float g_counts[NUM_EMB];
__device__ float g_loss_sum;

// ---------------------------------------------------------------------------
// k_init: per-code squared norms, zero the accumulators (re-runs on every
// graph replay, so state is always fresh).
// ---------------------------------------------------------------------------
__global__ void k_init(const float* __restrict__ weight) {
    int k = threadIdx.x;  // 1024 threads
    const float* w = weight + k * DIM;
    float s = 0.f;
#pragma unroll
    for (int d = 0; d < DIM; ++d) {
        float v = w[d];
        s = __fadd_rn(s, __fmul_rn(v, v));  // unfused: match jnp.sum(w**2)
    }
    g_ensq[k]   = s;
    g_counts[k] = 0.f;
    if (k == 0) g_loss_sum = 0.f;
}

// ---------------------------------------------------------------------------
// k_main: distances + argmin + gather + quantized write + loss partials
// ---------------------------------------------------------------------------
#define FMA2(acc, a, b) asm("fma.rn.f32x2 %0, %1, %2, %0;" : "+l"(acc) : "l"(a), "l"(b))

__global__ __launch_bounds__(256, 2)
void k_main(const float* __restrict__ inputs,
            const float* __restrict__ weight,
            float* __restrict__ out) {
    __shared__ float As[BM * PAD];
    __shared__ float Bs[BM * PAD];
    __shared__ float s_en[NUM_EMB];
    __shared__ float s_xsq[BM];
    __shared__ float red_s[BM * 16];
    __shared__ int   red_i[BM * 16];
    __shared__ int   s_idx[BM];
    __shared__ float s_part[256];

    const int tid  = threadIdx.x;
    const int blk  = blockIdx.x;
    const int tok0 = blk * BM;

    // Load token tile As[64][64] (8B granules, coalesced)
    {
        const ull* gsrc = (const ull*)(inputs + (size_t)tok0 * DIM);
#pragma unroll
        for (int it = 0; it < 8; ++it) {
            int e = tid + it * 256;          // 0..2047
            int row = e >> 5, q = e & 31;
            ((ull*)(As + row * PAD))[q] = gsrc[row * 32 + q];
        }
    }
    // Load code norms
#pragma unroll
    for (int it = 0; it < 4; ++it) s_en[tid + it * 256] = g_ensq[tid + it * 256];
    __syncthreads();

    // ||x||^2 per token — sequential, UNFUSED (replicate reference rounding)
    if (tid < BM) {
        const float* x = As + tid * PAD;
        float s = 0.f;
#pragma unroll
        for (int d = 0; d < DIM; ++d) {
            float v = x[d];
            s = __fadd_rn(s, __fmul_rn(v, v));
        }
        s_xsq[tid] = s;
    }
    __syncthreads();

    const int tx = tid & 15;   // code lane
    const int ty = tid >> 4;   // token lane

    float xq[4];
#pragma unroll
    for (int i = 0; i < 4; ++i) xq[i] = s_xsq[ty * 4 + i];

    float best[4];
    int   bidx[4];
#pragma unroll
    for (int i = 0; i < 4; ++i) { best[i] = 3.4e38f; bidx[i] = 0x7fffffff; }

    ull acc[16];
#pragma unroll
    for (int a = 0; a < 16; ++a) acc[a] = 0ull;

    const ull* a0 = (const ull*)(As + (ty * 4 + 0) * PAD);
    const ull* a1 = (const ull*)(As + (ty * 4 + 1) * PAD);
    const ull* a2 = (const ull*)(As + (ty * 4 + 2) * PAD);
    const ull* a3 = (const ull*)(As + (ty * 4 + 3) * PAD);

    for (int c = 0; c < 16; ++c) {
        __syncthreads();  // previous chunk's reads of Bs are done
        {
            const ull* gsrc = (const ull*)(weight + (size_t)(c * 64) * DIM);
#pragma unroll
            for (int it = 0; it < 8; ++it) {
                int e = tid + it * 256;
                int row = e >> 5, q = e & 31;
                ((ull*)(Bs + row * PAD))[q] = gsrc[row * 32 + q];
            }
        }
        __syncthreads();

        const ull* b0 = (const ull*)(Bs + (tx +  0) * PAD);
        const ull* b1 = (const ull*)(Bs + (tx + 16) * PAD);
        const ull* b2 = (const ull*)(Bs + (tx + 32) * PAD);
        const ull* b3 = (const ull*)(Bs + (tx + 48) * PAD);

#pragma unroll
        for (int dd = 0; dd < 32; ++dd) {
            ull A0 = a0[dd], A1 = a1[dd], A2 = a2[dd], A3 = a3[dd];
            ull B0 = b0[dd], B1 = b1[dd], B2 = b2[dd], B3 = b3[dd];
            FMA2(acc[ 0], A0, B0); FMA2(acc[ 1], A0, B1);
            FMA2(acc[ 2], A0, B2); FMA2(acc[ 3], A0, B3);
            FMA2(acc[ 4], A1, B0); FMA2(acc[ 5], A1, B1);
            FMA2(acc[ 6], A1, B2); FMA2(acc[ 7], A1, B3);
            FMA2(acc[ 8], A2, B0); FMA2(acc[ 9], A2, B1);
            FMA2(acc[10], A2, B2); FMA2(acc[11], A2, B3);
            FMA2(acc[12], A3, B0); FMA2(acc[13], A3, B1);
            FMA2(acc[14], A3, B2); FMA2(acc[15], A3, B3);
        }

        // Epilogue: score = fl(fl(xsq + ensq) - 2*dot)  (single rounding via FMA,
        // identical to reference since 2*dot is exact)
#pragma unroll
        for (int i = 0; i < 4; ++i) {
#pragma unroll
            for (int j = 0; j < 4; ++j) {
                ull v = acc[i * 4 + j];
                acc[i * 4 + j] = 0ull;
                unsigned lo = (unsigned)v, hi = (unsigned)(v >> 32);
                float dot = __fadd_rn(__uint_as_float(lo), __uint_as_float(hi));
                int idx = c * 64 + tx + j * 16;
                float t = __fadd_rn(xq[i], s_en[idx]);
                float s = fmaf(-2.f, dot, t);
                if (s < best[i] || (s == best[i] && idx < bidx[i])) {
                    best[i] = s; bidx[i] = idx;
                }
            }
        }
    }

    // Cross-thread argmin reduction per token (tie -> lowest index)
#pragma unroll
    for (int i = 0; i < 4; ++i) {
        red_s[(ty * 4 + i) * 16 + tx] = best[i];
        red_i[(ty * 4 + i) * 16 + tx] = bidx[i];
    }
    __syncthreads();

    if (tid < BM) {
        float bs = red_s[tid * 16];
        int   bi = red_i[tid * 16];
#pragma unroll
        for (int x = 1; x < 16; ++x) {
            float s  = red_s[tid * 16 + x];
            int   ix = red_i[tid * 16 + x];
            if (s < bs || (s == bs && ix < bi)) { bs = s; bi = ix; }
        }
        s_idx[tid] = bi;
        out[OFF_IDX + (size_t)(tok0 + tid)] = (float)bi;
        atomicAdd(&g_counts[bi], 1.f);
    }
    __syncthreads();

    // Gather codes -> quantized output (coalesced), accumulate squared diff
    float local = 0.f;
#pragma unroll
    for (int it = 0; it < 16; ++it) {
        int e = tid + it * 256;              // 0..4095
        int t = e >> 6, d = e & 63;
        float q = weight[(size_t)s_idx[t] * DIM + d];
        float x = As[t * PAD + d];
        out[OFF_Q + (size_t)(tok0 + t) * DIM + d] = q;
        float diff = q - x;
        local = fmaf(diff, diff, local);
    }
    s_part[tid] = local;
    __syncthreads();
    for (int off = 128; off > 0; off >>= 1) {
        if (tid < off) s_part[tid] += s_part[tid + off];
        __syncthreads();
    }
    if (tid == 0) atomicAdd(&g_loss_sum, s_part[0]);
}

// ---------------------------------------------------------------------------
// k_final: loss scalar + perplexity
// ---------------------------------------------------------------------------
__global__ void k_final(float* __restrict__ out) {
    __shared__ float sh[1024];
    int k = threadIdx.x;
    float p = g_counts[k] * (1.f / 65536.f);
    sh[k] = p * logf(p + 1e-10f);
    __syncthreads();
    for (int off = 512; off > 0; off >>= 1) {
        if (k < off) sh[k] += sh[k + off];
        __syncthreads();
    }
    if (k == 0) {
        // q_latent == e_latent numerically -> loss = 1.25 * mse
        out[0]       = 1.25f * g_loss_sum * (1.f / (float)(N_TOKENS * DIM));
        out[OFF_PPL] = expf(-sh[0]);
    }
}

// ---------------------------------------------------------------------------
extern "C" void kernel_launch(void* const* d_in, const int* in_sizes, int n_in,
                              void* d_out, int out_size) {
    const float* inputs = (const float*)d_in[0];   // [64,32,32,64] fp32
    const float* weight = (const float*)d_in[1];   // [1024,64] fp32
    float* out = (float*)d_out;

    k_init<<<1, 1024>>>(weight);
    k_main<<<N_TOKENS / BM, 256>>>(inputs, weight, out);
    k_final<<<1, 1024>>>(out);
}

// round 2
// speedup vs baseline: 1.0478x; 1.0478x over previous
#include <cuda_runtime.h>

// Problem constants
#define NUM_EMB   1024
#define DIM       64
#define N_TOKENS  65536
#define BM        128         // tokens per block
#define PAD       66          // smem row pitch in floats (conflict-free LDS.64)
#define NCHUNK    16          // 1024 codes / 64 per chunk

// Output layout (single fp32 buffer, tuple order flattened)
#define OFF_Q     1
#define OFF_PPL   (1 + N_TOKENS*DIM)
#define OFF_IDX   (2 + N_TOKENS*DIM)

typedef unsigned long long ull;

__device__ float g_ensq[NUM_EMB];
__device__ float g_counts[NUM_EMB];
__device__ float g_loss_sum;

// ---------------------------------------------------------------------------
// k_init: per-code squared norms (bit-identical sequential unfused order,
// now parallel across 8 blocks with coalesced smem staging) + zero accums.
// ---------------------------------------------------------------------------
__global__ void k_init(const float* __restrict__ weight) {
    __shared__ float sw[128 * PAD];
    const int tid = threadIdx.x;          // 128 threads
    const int b   = blockIdx.x;           // 8 blocks
    const float* g = weight + (size_t)b * 128 * DIM;
#pragma unroll
    for (int i = 0; i < 64; ++i) {        // coalesced global reads
        int e = tid + i * 128;
        sw[(e >> 6) * PAD + (e & 63)] = g[e];
    }
    __syncthreads();
    const float* x = sw + tid * PAD;
    float s = 0.f;
#pragma unroll
    for (int d = 0; d < DIM; ++d) {       // sequential, UNFUSED (match ref)
        float v = x[d];
        s = __fadd_rn(s, __fmul_rn(v, v));
    }
    const int k = b * 128 + tid;
    g_ensq[k]   = s;
    g_counts[k] = 0.f;
    if (k == 0) g_loss_sum = 0.f;
}

// ---------------------------------------------------------------------------
// k_main: distances (f32x2 FMA) + argmin + gather + loss partials
// ---------------------------------------------------------------------------
#define FMA2(acc, a, b) asm("fma.rn.f32x2 %0, %1, %2, %0;" : "+l"(acc) : "l"(a), "l"(b))

// dynamic smem layout (byte offsets)
#define SM_AS    0                         // As: BM*PAD floats   = 33792 B
#define SM_BS    33792                     // Bs: 2*64*PAD floats = 33792 B
#define SM_EN    (SM_BS + 2*64*PAD*4)      // 67584: code norms, 4096 B
#define SM_XSQ   (SM_EN + 4096)            // 71680: 128 floats
#define SM_REDS  (SM_XSQ + 512)            // 72192: BM*16 floats = 8192 B
#define SM_REDI  (SM_REDS + BM*16*4)       // 80384: BM*16 ints   = 8192 B
#define SM_IDX   (SM_REDI + BM*16*4)       // 88576: 128 ints
#define SM_PART  (SM_IDX + 512)            // 89088: 256 floats
#define SM_TOTAL (SM_PART + 1024)          // 90112 B total (2 CTA/SM fits)

__device__ __forceinline__ void cp8(unsigned saddr, const void* gaddr) {
    asm volatile("cp.async.ca.shared.global [%0], [%1], 8;" :: "r"(saddr), "l"(gaddr));
}
__device__ __forceinline__ void cp_commit() {
    asm volatile("cp.async.commit_group;" ::: "memory");
}
__device__ __forceinline__ void cp_wait1() {
    asm volatile("cp.async.wait_group 1;" ::: "memory");
}

__global__ __launch_bounds__(256, 2)
void k_main(const float* __restrict__ inputs,
            const float* __restrict__ weight,
            float* __restrict__ out) {
    extern __shared__ char smem_raw[];
    float* As    = (float*)(smem_raw + SM_AS);
    float* Bs    = (float*)(smem_raw + SM_BS);
    float* s_en  = (float*)(smem_raw + SM_EN);
    float* s_xsq = (float*)(smem_raw + SM_XSQ);
    float* red_s = (float*)(smem_raw + SM_REDS);
    int*   red_i = (int*)  (smem_raw + SM_REDI);
    int*   s_idx = (int*)  (smem_raw + SM_IDX);
    float* s_part= (float*)(smem_raw + SM_PART);

    const unsigned s_base = (unsigned)__cvta_generic_to_shared(smem_raw);
    const unsigned bs_addr = s_base + SM_BS;

    const int tid  = threadIdx.x;
    const int tok0 = blockIdx.x * BM;

    // --- load token tile As[128][64] (8B granules, coalesced) ---
    {
        const ull* gA = (const ull*)(inputs + (size_t)tok0 * DIM);
#pragma unroll
        for (int it = 0; it < 16; ++it) {
            int e = tid + it * 256;              // 0..4095
            int row = e >> 5, q = e & 31;
            ((ull*)(As + row * PAD))[q] = gA[row * 32 + q];
        }
    }
    // --- code norms ---
#pragma unroll
    for (int it = 0; it < 4; ++it) s_en[tid + it * 256] = g_ensq[tid + it * 256];

    // --- prefetch B chunk 0 (cp.async) ---
    const ull* gW = (const ull*)weight;
#pragma unroll
    for (int it = 0; it < 8; ++it) {
        int e = tid + it * 256;                  // 0..2047
        int row = e >> 5, q = e & 31;
        cp8(bs_addr + (unsigned)((row * PAD + q * 2) * 4), gW + row * 32 + q);
    }
    cp_commit();

    __syncthreads();

    // --- ||x||^2 per token: sequential UNFUSED (replicate reference) ---
    if (tid < BM) {
        const float* x = As + tid * PAD;
        float s = 0.f;
#pragma unroll
        for (int d = 0; d < DIM; ++d) {
            float v = x[d];
            s = __fadd_rn(s, __fmul_rn(v, v));
        }
        s_xsq[tid] = s;
    }
    __syncthreads();

    const int tx = tid & 15;   // code lane (16)
    const int ty = tid >> 4;   // token-group lane (16), 8 tokens each

    float xq[8];
#pragma unroll
    for (int i = 0; i < 8; ++i) xq[i] = s_xsq[ty * 8 + i];

    float best[8];
    int   bidx[8];
#pragma unroll
    for (int i = 0; i < 8; ++i) { best[i] = 3.4e38f; bidx[i] = 0x7fffffff; }

    ull acc[32];
#pragma unroll
    for (int a = 0; a < 32; ++a) acc[a] = 0ull;

    const ull* a_base = (const ull*)(As + (ty * 8) * PAD);

    for (int c = 0; c < NCHUNK; ++c) {
        // prefetch chunk c+1 into the other buffer (empty group on last iter)
        if (c + 1 < NCHUNK) {
            unsigned dst = bs_addr + (unsigned)(((c + 1) & 1) * 64 * PAD * 4);
            const ull* src = gW + (size_t)(c + 1) * 2048;
#pragma unroll
            for (int it = 0; it < 8; ++it) {
                int e = tid + it * 256;
                int row = e >> 5, q = e & 31;
                cp8(dst + (unsigned)((row * PAD + q * 2) * 4), src + row * 32 + q);
            }
        }
        cp_commit();
        cp_wait1();            // chunk c's group is complete
        __syncthreads();       // ...and visible to all threads

        const ull* b_base = (const ull*)(Bs + (c & 1) * (64 * PAD) + tx * PAD);

#pragma unroll 8
        for (int dd = 0; dd < 32; ++dd) {
            ull B0 = b_base[dd];
            ull B1 = b_base[dd + 16 * 33];
            ull B2 = b_base[dd + 32 * 33];
            ull B3 = b_base[dd + 48 * 33];
#pragma unroll
            for (int i = 0; i < 8; ++i) {
                ull A = a_base[dd + i * 33];
                FMA2(acc[i * 4 + 0], A, B0);
                FMA2(acc[i * 4 + 1], A, B1);
                FMA2(acc[i * 4 + 2], A, B2);
                FMA2(acc[i * 4 + 3], A, B3);
            }
        }

        // Epilogue: score = fl(fl(xsq + ensq) - 2*dot), single rounding via FMA
#pragma unroll
        for (int i = 0; i < 8; ++i) {
#pragma unroll
            for (int j = 0; j < 4; ++j) {
                ull v = acc[i * 4 + j];
                acc[i * 4 + j] = 0ull;
                unsigned lo = (unsigned)v, hi = (unsigned)(v >> 32);
                float dot = __fadd_rn(__uint_as_float(lo), __uint_as_float(hi));
                int idx = c * 64 + tx + j * 16;
                float t = __fadd_rn(xq[i], s_en[idx]);
                float s = fmaf(-2.f, dot, t);
                if (s < best[i] || (s == best[i] && idx < bidx[i])) {
                    best[i] = s; bidx[i] = idx;
                }
            }
        }
        __syncthreads();       // all reads of buf[c&1] done before overwrite
    }

    // --- cross-thread argmin per token (tie -> lowest index) ---
#pragma unroll
    for (int i = 0; i < 8; ++i) {
        red_s[(ty * 8 + i) * 16 + tx] = best[i];
        red_i[(ty * 8 + i) * 16 + tx] = bidx[i];
    }
    __syncthreads();

    if (tid < BM) {
        float bs = red_s[tid * 16];
        int   bi = red_i[tid * 16];
#pragma unroll
        for (int x = 1; x < 16; ++x) {
            float s  = red_s[tid * 16 + x];
            int   ix = red_i[tid * 16 + x];
            if (s < bs || (s == bs && ix < bi)) { bs = s; bi = ix; }
        }
        s_idx[tid] = bi;
        out[OFF_IDX + (size_t)(tok0 + tid)] = (float)bi;
        atomicAdd(&g_counts[bi], 1.f);
    }
    __syncthreads();

    // --- gather codes -> quantized output, accumulate squared diff ---
    float local = 0.f;
#pragma unroll
    for (int it = 0; it < 32; ++it) {
        int e = tid + it * 256;              // 0..8191
        int t = e >> 6, d = e & 63;
        float q = weight[(size_t)s_idx[t] * DIM + d];
        float x = As[t * PAD + d];
        out[OFF_Q + (size_t)(tok0 + t) * DIM + d] = q;
        float diff = q - x;
        local = fmaf(diff, diff, local);
    }
    s_part[tid] = local;
    __syncthreads();
    for (int off = 128; off > 0; off >>= 1) {
        if (tid < off) s_part[tid] += s_part[tid + off];
        __syncthreads();
    }
    if (tid == 0) atomicAdd(&g_loss_sum, s_part[0]);
}

// ---------------------------------------------------------------------------
// k_final: loss scalar + perplexity
// ---------------------------------------------------------------------------
__global__ void k_final(float* __restrict__ out) {
    __shared__ float sh[1024];
    int k = threadIdx.x;
    float p = g_counts[k] * (1.f / 65536.f);
    sh[k] = p * logf(p + 1e-10f);
    __syncthreads();
    for (int off = 512; off > 0; off >>= 1) {
        if (k < off) sh[k] += sh[k + off];
        __syncthreads();
    }
    if (k == 0) {
        out[0]       = 1.25f * g_loss_sum * (1.f / (float)(N_TOKENS * DIM));
        out[OFF_PPL] = expf(-sh[0]);
    }
}

// ---------------------------------------------------------------------------
extern "C" void kernel_launch(void* const* d_in, const int* in_sizes, int n_in,
                              void* d_out, int out_size) {
    const float* inputs = (const float*)d_in[0];   // [64,32,32,64] fp32
    const float* weight = (const float*)d_in[1];   // [1024,64] fp32
    float* out = (float*)d_out;

    cudaFuncSetAttribute(k_main, cudaFuncAttributeMaxDynamicSharedMemorySize, SM_TOTAL);
    k_init<<<8, 128>>>(weight);
    k_main<<<N_TOKENS / BM, 256, SM_TOTAL>>>(inputs, weight, out);
    k_final<<<1, 1024>>>(out);
}